// round 6
// baseline (speedup 1.0000x reference)
#include <cuda_runtime.h>
#include <math.h>

#define BATCH     16
#define MEM_DIM   172
#define TOK       4096
#define TIME_DIM  100
#define LEN_TOK   512
#define NROWS     44        // 22 cat + 21 texp + 1 pad
#define ASTRIDE   24        // padded smem row stride (16B aligned)
#define TILE      128       // columns per CTA

typedef unsigned long long ull;

__device__ __forceinline__ ull pack2(float lo, float hi) {
    ull d; asm("mov.b64 %0, {%1, %2};" : "=l"(d) : "f"(lo), "f"(hi)); return d;
}
__device__ __forceinline__ void unpack2(ull v, float& lo, float& hi) {
    asm("mov.b64 {%0, %1}, %2;" : "=f"(lo), "=f"(hi) : "l"(v));
}
__device__ __forceinline__ ull fma2(ull a, ull b, ull c) {
    ull d; asm("fma.rn.f32x2 %0, %1, %2, %3;" : "=l"(d) : "l"(a), "l"(b), "l"(c)); return d;
}

// ---------------------------------------------------------------------------
// One fused kernel. grid (16 batches, 32 col-tiles of 128), block 512.
//   threads   0-255 : mem projection  (128 cols x 2 k-slices over MEM_DIM)
//   threads 256-511 : time projection (128 cols x 2 k-slices over TIME_DIM)
//   then all 512    : scatter 3*512 token rows straight from smem (STG.128 stcs)
// res rows: 0..21 = cat_mem, 22..42 = texp, 43 = pad.
// ---------------------------------------------------------------------------
__global__ void __launch_bounds__(512)
k_fused(const float* __restrict__ memory,
        const int*   __restrict__ src_nodes,
        const int*   __restrict__ dst_nodes,
        const int*   __restrict__ src_nei,
        const int*   __restrict__ dst_nei,
        const float* __restrict__ timestamps,
        const float* __restrict__ se,
        const float* __restrict__ de,
        const float* __restrict__ W1, const float* __restrict__ b1,
        const float* __restrict__ W2, const float* __restrict__ b2,
        const float* __restrict__ Wt, const float* __restrict__ bt,
        const float* __restrict__ w_time,
        const float* __restrict__ phase,
        float*       __restrict__ out)
{
    __shared__ float Ash[MEM_DIM * ASTRIDE];    // [k][slot]: 2i = row i, 2i+1 = row 11+i
    __shared__ float Ten[TIME_DIM * ASTRIDE];   // [k][row],  row 21 = pad 0
    __shared__ float res[NROWS * TILE];         // [44][128] final projected rows

    const int b    = blockIdx.x;
    const int tile = blockIdx.y;
    const int tid  = threadIdx.x;

    // ---------------- staging (all 512) ----------------
    for (int i = tid; i < 22 * MEM_DIM; i += 512) {
        int r = i / MEM_DIM;
        int k = i - r * MEM_DIM;
        int node;
        if (r == 0)       node = src_nodes[b];
        else if (r < 11)  node = dst_nei[b * 10 + r - 1];
        else if (r == 11) node = dst_nodes[b];
        else              node = src_nei[b * 10 + r - 12];
        int slot = (r < 11) ? (2 * r) : (2 * (r - 11) + 1);
        Ash[k * ASTRIDE + slot] = memory[(size_t)node * MEM_DIM + k];
    }
    const float t0 = timestamps[b];
    for (int i = tid; i < TIME_DIM * 22; i += 512) {
        int k = i / 22;
        int r = i - k * 22;
        float v = 0.f;
        if (r < 21) {
            float delta;
            if (r == 0)      delta = 0.f;
            else if (r < 11) delta = t0 - se[b * 10 + r - 1];
            else             delta = t0 - de[b * 10 + r - 11];
            v = cosf(delta * w_time[k] + phase[k]);
        }
        Ten[k * ASTRIDE + r] = v;
    }
    __syncthreads();

    // ---------------- projection ----------------
    const int cl    = tid & 127;
    const int slice = (tid >> 7) & 1;
    const int grpT  = tid >> 8;                 // 0 = mem group, 1 = time group
    const int col   = tile * TILE + cl;

    ull acc[11];

    if (grpT == 0) {
        // ---- mem projection: pairs (row p, row 11+p) vs {W1, W2} ----
        const ull bi = pack2(b1[col], b2[col]);
#pragma unroll
        for (int p = 0; p < 11; p++) acc[p] = slice == 0 ? bi : 0ull;

        const int k0 = slice ? 84 : 0;
        const int k1 = slice ? 172 : 84;

        float w1b[4], w2b[4];
#pragma unroll
        for (int i = 0; i < 4; i++) {
            w1b[i] = W1[(size_t)(k0 + i) * TOK + col];
            w2b[i] = W2[(size_t)(k0 + i) * TOK + col];
        }
#pragma unroll 4
        for (int k = k0; k < k1; k++) {
            const int s = (k - k0) & 3;
            ull w = pack2(w1b[s], w2b[s]);
            int kp = k + 4; if (kp >= k1) kp = k1 - 1;
            w1b[s] = W1[(size_t)kp * TOK + col];
            w2b[s] = W2[(size_t)kp * TOK + col];

            const float* a = Ash + k * ASTRIDE;
#pragma unroll
            for (int q = 0; q < 5; q++) {
                ulonglong2 v = *(const ulonglong2*)(a + 4 * q);
                acc[2 * q]     = fma2(v.x, w, acc[2 * q]);
                acc[2 * q + 1] = fma2(v.y, w, acc[2 * q + 1]);
            }
            acc[10] = fma2(*(const ull*)(a + 20), w, acc[10]);
        }
        if (slice) {                            // partial -> res
#pragma unroll
            for (int p = 0; p < 11; p++) {
                float lo, hi; unpack2(acc[p], lo, hi);
                res[p * TILE + cl]        = lo;
                res[(11 + p) * TILE + cl] = hi;
            }
        }
    } else {
        // ---- time projection: pairs (row 2p, row 2p+1) vs {wt, wt} ----
        const float btc = bt[col];
        const ull bi = pack2(btc, btc);
#pragma unroll
        for (int p = 0; p < 11; p++) acc[p] = slice == 0 ? bi : 0ull;

        const int k0 = slice ? 48 : 0;
        const int k1 = slice ? 100 : 48;

        float wtb[4];
#pragma unroll
        for (int i = 0; i < 4; i++)
            wtb[i] = Wt[(size_t)(k0 + i) * TOK + col];
#pragma unroll 4
        for (int k = k0; k < k1; k++) {
            const int s = (k - k0) & 3;
            ull w = pack2(wtb[s], wtb[s]);
            int kp = k + 4; if (kp >= k1) kp = k1 - 1;
            wtb[s] = Wt[(size_t)kp * TOK + col];

            const float* a = Ten + k * ASTRIDE;
#pragma unroll
            for (int q = 0; q < 5; q++) {
                ulonglong2 v = *(const ulonglong2*)(a + 4 * q);
                acc[2 * q]     = fma2(v.x, w, acc[2 * q]);
                acc[2 * q + 1] = fma2(v.y, w, acc[2 * q + 1]);
            }
            acc[10] = fma2(*(const ull*)(a + 20), w, acc[10]);
        }
        if (slice) {
#pragma unroll
            for (int p = 0; p < 11; p++) {
                float lo, hi; unpack2(acc[p], lo, hi);
                res[(22 + 2 * p) * TILE + cl] = lo;
                res[(23 + 2 * p) * TILE + cl] = hi;   // p=10 -> pad row 43
            }
        }
    }
    __syncthreads();

    // slice-0 threads add slice-1 partials and write finals
    if (slice == 0) {
        if (grpT == 0) {
#pragma unroll
            for (int p = 0; p < 11; p++) {
                float lo, hi; unpack2(acc[p], lo, hi);
                res[p * TILE + cl]        += lo;
                res[(11 + p) * TILE + cl] += hi;
            }
        } else {
#pragma unroll
            for (int p = 0; p < 11; p++) {
                float lo, hi; unpack2(acc[p], lo, hi);
                res[(22 + 2 * p) * TILE + cl] += lo;
                res[(23 + 2 * p) * TILE + cl] += hi;
            }
        }
    }
    __syncthreads();

    // ---------------- scatter (all 512 threads) ----------------
    const int lane = tid & 31;                  // float4 lane: 32 x 16B = 128 cols
    const int grp  = tid >> 5;                  // 16 token groups of 32
    const float4* res4 = (const float4*)res;    // [44][32]
    float4* outv = (float4*)out;
    const int vrow = TOK / 4;                   // 1024
    const size_t T = (size_t)BATCH * LEN_TOK * vrow;
    const size_t obase = (size_t)(b * LEN_TOK) * vrow + tile * 32 + lane;

#pragma unroll 4
    for (int it = 0; it < 32; it++) {
        const int t = grp * 32 + it;
        int s, d, tm;
        if (t == 0)        { s = 0;  d = 11;    tm = 0;      }
        else if (t < 15)   { s = 0;  d = 0;     tm = 0;      }
        else if (t < 225)  { int j = (t - 15)  / 21; s = 0;  d = 12 + j; tm = 1 + j;  }
        else if (t < 239)  { s = 11; d = 11;    tm = 0;      }
        else if (t < 449)  { int j = (t - 239) / 21; s = 11; d = 1 + j;  tm = 11 + j; }
        else               { s = 0;  d = 11;    tm = 0;      }

        float4 vs = res4[s * 32 + lane];
        float4 vd = res4[d * 32 + lane];
        float4 vt = res4[(22 + tm) * 32 + lane];
        const size_t o = obase + (size_t)t * vrow;
        __stcs(&outv[o],         vs);
        __stcs(&outv[o + T],     vd);
        __stcs(&outv[o + 2 * T], vt);
    }
}

// ---------------------------------------------------------------------------
extern "C" void kernel_launch(void* const* d_in, const int* in_sizes, int n_in,
                              void* d_out, int out_size)
{
    const float* memory      = (const float*)d_in[0];
    const int*   src_nodes   = (const int*)  d_in[1];
    const int*   dst_nodes   = (const int*)  d_in[2];
    const int*   src_nei     = (const int*)  d_in[3];
    const int*   dst_nei     = (const int*)  d_in[4];
    const float* timestamps  = (const float*)d_in[5];
    const float* se          = (const float*)d_in[6];
    const float* de          = (const float*)d_in[7];
    const float* W1          = (const float*)d_in[8];
    const float* b1          = (const float*)d_in[9];
    const float* W2          = (const float*)d_in[10];
    const float* b2          = (const float*)d_in[11];
    const float* Wt          = (const float*)d_in[12];
    const float* bt          = (const float*)d_in[13];
    const float* w_time      = (const float*)d_in[14];
    const float* phase       = (const float*)d_in[15];
    float* out = (float*)d_out;

    k_fused<<<dim3(BATCH, TOK / TILE), 512>>>(memory, src_nodes, dst_nodes,
                                              src_nei, dst_nei,
                                              timestamps, se, de,
                                              W1, b1, W2, b2, Wt, bt,
                                              w_time, phase, out);
}

// round 7
// speedup vs baseline: 1.4000x; 1.4000x over previous
#include <cuda_runtime.h>
#include <math.h>

#define BATCH     16
#define MEM_DIM   172
#define TOK       4096
#define TIME_DIM  100
#define LEN_TOK   512
#define NROWS     44        // 22 cat + 21 texp + 1 pad
#define ASTRIDE   24        // padded smem row stride (16B aligned)
#define NGROUPS   4
#define GBATCH    (BATCH / NGROUPS)   // 4 batches per pipeline group

typedef unsigned long long ull;

// Projected rows scratch: [batch][44][4096] f32 = 11.5 MB (L2-resident).
__device__ float g_res[BATCH * NROWS * TOK];

__device__ __forceinline__ ull pack2(float lo, float hi) {
    ull d; asm("mov.b64 %0, {%1, %2};" : "=l"(d) : "f"(lo), "f"(hi)); return d;
}
__device__ __forceinline__ void unpack2(ull v, float& lo, float& hi) {
    asm("mov.b64 {%0, %1}, %2;" : "=f"(lo), "=f"(hi) : "l"(v));
}
__device__ __forceinline__ ull fma2(ull a, ull b, ull c) {
    ull d; asm("fma.rn.f32x2 %0, %1, %2, %3;" : "=l"(d) : "l"(a), "l"(b), "l"(c)); return d;
}
__device__ __forceinline__ ull add2(ull a, ull b) {
    ull d; asm("add.rn.f32x2 %0, %1, %2;" : "=l"(d) : "l"(a), "l"(b)); return d;
}

// ---------------------------------------------------------------------------
// Kernel A: projections for GBATCH batches. grid (GBATCH, 32 tiles of 128),
// block 256 = 128 cols x 2 k-slices. Depth-4 register prefetch of W.
// g_res rows: 0..21 = cat_mem, 22..42 = texp, 43 = pad.
// ---------------------------------------------------------------------------
__global__ void __launch_bounds__(256)
k_proj(const float* __restrict__ memory,
       const int*   __restrict__ src_nodes,
       const int*   __restrict__ dst_nodes,
       const int*   __restrict__ src_nei,
       const int*   __restrict__ dst_nei,
       const float* __restrict__ timestamps,
       const float* __restrict__ se,
       const float* __restrict__ de,
       const float* __restrict__ W1, const float* __restrict__ b1,
       const float* __restrict__ W2, const float* __restrict__ b2,
       const float* __restrict__ Wt, const float* __restrict__ bt,
       const float* __restrict__ w_time,
       const float* __restrict__ phase,
       int b0)
{
    __shared__ float Ash[MEM_DIM * ASTRIDE];    // [k][slot]: 2i=row i, 2i+1=row 11+i
    __shared__ float Ten[TIME_DIM * ASTRIDE];   // [k][row], row 21 = pad 0
    __shared__ ull   red[128 * 11];             // cross-slice partials

    const int b     = b0 + blockIdx.x;
    const int tile  = blockIdx.y;
    const int tid   = threadIdx.x;
    const int cl    = tid & 127;
    const int slice = tid >> 7;                 // 0 or 1
    const int col   = tile * 128 + cl;

    // ---- staging ----
    for (int i = tid; i < 22 * MEM_DIM; i += 256) {
        int r = i / MEM_DIM;
        int k = i - r * MEM_DIM;
        int node;
        if (r == 0)       node = src_nodes[b];
        else if (r < 11)  node = dst_nei[b * 10 + r - 1];
        else if (r == 11) node = dst_nodes[b];
        else              node = src_nei[b * 10 + r - 12];
        int slot = (r < 11) ? (2 * r) : (2 * (r - 11) + 1);
        Ash[k * ASTRIDE + slot] = memory[(size_t)node * MEM_DIM + k];
    }
    const float t0 = timestamps[b];
    for (int i = tid; i < TIME_DIM * 22; i += 256) {
        int k = i / 22;
        int r = i - k * 22;
        float v = 0.f;
        if (r < 21) {
            float delta;
            if (r == 0)      delta = 0.f;
            else if (r < 11) delta = t0 - se[b * 10 + r - 1];
            else             delta = t0 - de[b * 10 + r - 11];
            v = cosf(delta * w_time[k] + phase[k]);
        }
        Ten[k * ASTRIDE + r] = v;
    }
    __syncthreads();

    float* resb = g_res + (size_t)b * NROWS * TOK + col;

    // ---- mem projection: pairs (row p, row 11+p) vs {W1, W2} ----
    {
        ull acc[11];
        const ull bi = pack2(b1[col], b2[col]);
#pragma unroll
        for (int p = 0; p < 11; p++) acc[p] = slice == 0 ? bi : 0ull;

        const int k0 = slice ? 84 : 0;
        const int k1 = slice ? 172 : 84;

        float w1b[4], w2b[4];
#pragma unroll
        for (int i = 0; i < 4; i++) {
            w1b[i] = W1[(size_t)(k0 + i) * TOK + col];
            w2b[i] = W2[(size_t)(k0 + i) * TOK + col];
        }
#pragma unroll 4
        for (int k = k0; k < k1; k++) {
            const int s = (k - k0) & 3;
            ull w = pack2(w1b[s], w2b[s]);
            int kp = k + 4; if (kp >= k1) kp = k1 - 1;   // clamped prefetch
            w1b[s] = W1[(size_t)kp * TOK + col];
            w2b[s] = W2[(size_t)kp * TOK + col];

            const float* a = Ash + k * ASTRIDE;
#pragma unroll
            for (int q = 0; q < 5; q++) {
                ulonglong2 v = *(const ulonglong2*)(a + 4 * q);
                acc[2 * q]     = fma2(v.x, w, acc[2 * q]);
                acc[2 * q + 1] = fma2(v.y, w, acc[2 * q + 1]);
            }
            acc[10] = fma2(*(const ull*)(a + 20), w, acc[10]);
        }

        if (slice) {
#pragma unroll
            for (int p = 0; p < 11; p++) red[cl * 11 + p] = acc[p];
        }
        __syncthreads();
        if (slice == 0) {
#pragma unroll
            for (int p = 0; p < 11; p++) {
                acc[p] = add2(acc[p], red[cl * 11 + p]);
                float lo, hi; unpack2(acc[p], lo, hi);
                resb[(size_t)p * TOK]        = lo;
                resb[(size_t)(11 + p) * TOK] = hi;
            }
        }
        __syncthreads();   // red reused below
    }

    // ---- time projection: pairs (row 2p, row 2p+1) vs {wt, wt} ----
    {
        ull acc[11];
        const float btc = bt[col];
        const ull bi = pack2(btc, btc);
#pragma unroll
        for (int p = 0; p < 11; p++) acc[p] = slice == 0 ? bi : 0ull;

        const int k0 = slice ? 48 : 0;
        const int k1 = slice ? 100 : 48;

        float wtb[4];
#pragma unroll
        for (int i = 0; i < 4; i++)
            wtb[i] = Wt[(size_t)(k0 + i) * TOK + col];
#pragma unroll 4
        for (int k = k0; k < k1; k++) {
            const int s = (k - k0) & 3;
            ull w = pack2(wtb[s], wtb[s]);
            int kp = k + 4; if (kp >= k1) kp = k1 - 1;
            wtb[s] = Wt[(size_t)kp * TOK + col];

            const float* a = Ten + k * ASTRIDE;
#pragma unroll
            for (int q = 0; q < 5; q++) {
                ulonglong2 v = *(const ulonglong2*)(a + 4 * q);
                acc[2 * q]     = fma2(v.x, w, acc[2 * q]);
                acc[2 * q + 1] = fma2(v.y, w, acc[2 * q + 1]);
            }
            acc[10] = fma2(*(const ull*)(a + 20), w, acc[10]);
        }

        if (slice) {
#pragma unroll
            for (int p = 0; p < 11; p++) red[cl * 11 + p] = acc[p];
        }
        __syncthreads();
        if (slice == 0) {
#pragma unroll
            for (int p = 0; p < 11; p++) {
                acc[p] = add2(acc[p], red[cl * 11 + p]);
                float lo, hi; unpack2(acc[p], lo, hi);
                resb[(size_t)(22 + 2 * p) * TOK] = lo;
                resb[(size_t)(23 + 2 * p) * TOK] = hi;   // p=10 -> pad row 43
            }
        }
    }
}

// ---------------------------------------------------------------------------
// Kernel B: scatter for GBATCH batches. grid (GBATCH, 16 tiles, 8 token-slices),
// block 256 = 64 float4-lanes x 4 token-groups of 16. Streaming stores.
// ---------------------------------------------------------------------------
__global__ void __launch_bounds__(256)
k_scat(float* __restrict__ out, int b0)
{
    __shared__ float4 sres[NROWS * 64];     // 45056 B

    const int b     = b0 + blockIdx.x;
    const int tile  = blockIdx.y;
    const int slice = blockIdx.z;
    const int tid   = threadIdx.x;
    const int lane  = tid & 63;
    const int grp   = tid >> 6;

    const float4* gresv = (const float4*)g_res;
    const int vrow = TOK / 4;               // 1024

#pragma unroll
    for (int i = tid; i < NROWS * 64; i += 256)
        sres[i] = gresv[(size_t)(b * NROWS + (i >> 6)) * vrow + tile * 64 + (i & 63)];
    __syncthreads();

    float4* outv = (float4*)out;
    const size_t T = (size_t)BATCH * LEN_TOK * vrow;
    const size_t obase = (size_t)(b * LEN_TOK) * vrow + tile * 64 + lane;
    const int t0 = slice * 64 + grp * 16;

#pragma unroll 4
    for (int it = 0; it < 16; it++) {
        const int t = t0 + it;
        int s, d, tm;
        if (t == 0)        { s = 0;  d = 11;    tm = 0;      }
        else if (t < 15)   { s = 0;  d = 0;     tm = 0;      }
        else if (t < 225)  { int j = (t - 15)  / 21; s = 0;  d = 12 + j; tm = 1 + j;  }
        else if (t < 239)  { s = 11; d = 11;    tm = 0;      }
        else if (t < 449)  { int j = (t - 239) / 21; s = 11; d = 1 + j;  tm = 11 + j; }
        else               { s = 0;  d = 11;    tm = 0;      }

        float4 vs = sres[s * 64 + lane];
        float4 vd = sres[d * 64 + lane];
        float4 vt = sres[(22 + tm) * 64 + lane];
        const size_t o = obase + (size_t)t * vrow;
        __stcs(&outv[o],         vs);
        __stcs(&outv[o + T],     vd);
        __stcs(&outv[o + 2 * T], vt);
    }
}

// ---------------------------------------------------------------------------
// Pipelined launch: proj(g) on the main (captured) stream, scat(g) on a second
// stream gated by an event — scat(g) overlaps proj(g+1). Fork-join pattern is
// graph-capture legal; streams/events are host objects (no device allocation).
// ---------------------------------------------------------------------------
extern "C" void kernel_launch(void* const* d_in, const int* in_sizes, int n_in,
                              void* d_out, int out_size)
{
    const float* memory      = (const float*)d_in[0];
    const int*   src_nodes   = (const int*)  d_in[1];
    const int*   dst_nodes   = (const int*)  d_in[2];
    const int*   src_nei     = (const int*)  d_in[3];
    const int*   dst_nei     = (const int*)  d_in[4];
    const float* timestamps  = (const float*)d_in[5];
    const float* se          = (const float*)d_in[6];
    const float* de          = (const float*)d_in[7];
    const float* W1          = (const float*)d_in[8];
    const float* b1          = (const float*)d_in[9];
    const float* W2          = (const float*)d_in[10];
    const float* b2          = (const float*)d_in[11];
    const float* Wt          = (const float*)d_in[12];
    const float* bt          = (const float*)d_in[13];
    const float* w_time      = (const float*)d_in[14];
    const float* phase       = (const float*)d_in[15];
    float* out = (float*)d_out;

    static cudaStream_t s1 = nullptr;
    static cudaEvent_t  ep[NGROUPS];
    static cudaEvent_t  ej;
    if (s1 == nullptr) {
        cudaStreamCreateWithFlags(&s1, cudaStreamNonBlocking);
        for (int g = 0; g < NGROUPS; g++)
            cudaEventCreateWithFlags(&ep[g], cudaEventDisableTiming);
        cudaEventCreateWithFlags(&ej, cudaEventDisableTiming);
    }

    for (int g = 0; g < NGROUPS; g++) {
        k_proj<<<dim3(GBATCH, TOK / 128), 256>>>(memory, src_nodes, dst_nodes,
                                                 src_nei, dst_nei,
                                                 timestamps, se, de,
                                                 W1, b1, W2, b2, Wt, bt,
                                                 w_time, phase, g * GBATCH);
        cudaEventRecord(ep[g], 0);
        cudaStreamWaitEvent(s1, ep[g], 0);
        k_scat<<<dim3(GBATCH, TOK / 256, 8), 256, 0, s1>>>(out, g * GBATCH);
    }
    cudaEventRecord(ej, s1);
    cudaStreamWaitEvent(0, ej, 0);
}

// round 8
// speedup vs baseline: 2.0678x; 1.4769x over previous
#include <cuda_runtime.h>
#include <math.h>
#include <stdint.h>

#define BATCH     16
#define MEM_DIM   172
#define KPAD      176       // MEM_DIM padded to multiple of 16 (2 slices x 8-k stages)
#define TOK       4096
#define TIME_DIM  100
#define TPAD      112       // TIME_DIM padded
#define LEN_TOK   512
#define NROWS     44        // 22 cat + 21 texp + 1 pad
#define ASTRIDE   24        // padded smem row stride (16B aligned)

typedef unsigned long long ull;

// Projected rows scratch: [batch][44][4096] f32 = 11.5 MB (L2-resident).
__device__ __align__(16) float g_res[BATCH * NROWS * TOK];

__device__ __forceinline__ ull pack2(float lo, float hi) {
    ull d; asm("mov.b64 %0, {%1, %2};" : "=l"(d) : "f"(lo), "f"(hi)); return d;
}
__device__ __forceinline__ void unpack2(ull v, float& lo, float& hi) {
    asm("mov.b64 {%0, %1}, %2;" : "=f"(lo), "=f"(hi) : "l"(v));
}
__device__ __forceinline__ ull fma2(ull a, ull b, ull c) {
    ull d; asm("fma.rn.f32x2 %0, %1, %2, %3;" : "=l"(d) : "l"(a), "l"(b), "l"(c)); return d;
}
__device__ __forceinline__ ull add2(ull a, ull b) {
    ull d; asm("add.rn.f32x2 %0, %1, %2;" : "=l"(d) : "l"(a), "l"(b)); return d;
}
__device__ __forceinline__ uint32_t s2u(const void* p) {
    return (uint32_t)__cvta_generic_to_shared(p);
}
__device__ __forceinline__ void cp16(uint32_t dst, const void* src) {
    asm volatile("cp.async.cg.shared.global [%0], [%1], 16;" :: "r"(dst), "l"(src));
}
__device__ __forceinline__ void cp_commit() { asm volatile("cp.async.commit_group;"); }
template<int N> __device__ __forceinline__ void cp_wait() {
    asm volatile("cp.async.wait_group %0;" :: "n"(N) : "memory");
}

// Stage fill: 8 k-rows x 128 cols of W1 and W2 -> buf[k][0..127]=W1, [k][128..255]=W2.
// 512 x 16B chunks over 128 threads = 4 per thread.
__device__ __forceinline__ void fill_w(float* buf, const float* W1, const float* W2,
                                       int kbase, int colbase, int cl)
{
#pragma unroll
    for (int j = 0; j < 4; j++) {
        int c   = cl + 128 * j;           // 0..511
        int mat = c >> 8;                 // 0 = W1, 1 = W2
        int k   = (c >> 5) & 7;
        int c16 = c & 31;
        int krow = kbase + k; if (krow > MEM_DIM - 1) krow = MEM_DIM - 1;  // A row is 0 there
        const float* src = (mat ? W2 : W1) + (size_t)krow * TOK + colbase + c16 * 4;
        cp16(s2u(buf + k * 256 + mat * 128 + c16 * 4), src);
    }
}

// Stage fill for Wt: 8 k-rows x 128 cols. 256 chunks / 128 threads = 2 per thread.
__device__ __forceinline__ void fill_t(float* buf, const float* Wt,
                                       int kbase, int colbase, int cl)
{
#pragma unroll
    for (int j = 0; j < 2; j++) {
        int c   = cl + 128 * j;           // 0..255
        int k   = c >> 5;
        int c16 = c & 31;
        int krow = kbase + k; if (krow > TIME_DIM - 1) krow = TIME_DIM - 1;
        cp16(s2u(buf + k * 128 + c16 * 4), Wt + (size_t)krow * TOK + colbase + c16 * 4);
    }
}

// Smem layout (dynamic, 60416 B):
//   Ash  [176][24] f32  16896 B   (aliased as red after each GEMM loop)
//   Ten  [112][24] f32  10752 B
//   Wbuf [2 slices][2 stages][8][256] f32  32768 B  (time loop reuses low half)
#define ASH_B  (KPAD * ASTRIDE * 4)
#define TEN_B  (TPAD * ASTRIDE * 4)
#define WB_B   (2 * 2 * 8 * 256 * 4)
#define SMEM_B (ASH_B + TEN_B + WB_B)

// ---------------------------------------------------------------------------
// Kernel A: projections. grid (16 b, 32 tiles of 128 cols), block 256
// (= 128 cols x 2 k-slices). cp.async double-buffered W stream.
// g_res rows: 0..21 = cat_mem, 22..42 = texp, 43 = pad.
// ---------------------------------------------------------------------------
__global__ void __launch_bounds__(256)
k_proj(const float* __restrict__ memory,
       const int*   __restrict__ src_nodes,
       const int*   __restrict__ dst_nodes,
       const int*   __restrict__ src_nei,
       const int*   __restrict__ dst_nei,
       const float* __restrict__ timestamps,
       const float* __restrict__ se,
       const float* __restrict__ de,
       const float* __restrict__ W1, const float* __restrict__ b1,
       const float* __restrict__ W2, const float* __restrict__ b2,
       const float* __restrict__ Wt, const float* __restrict__ bt,
       const float* __restrict__ w_time,
       const float* __restrict__ phase)
{
    extern __shared__ __align__(16) char sraw[];
    float* Ash = (float*)sraw;                     // [176][24]: slot 2i=row i, 2i+1=row 11+i
    float* Ten = (float*)(sraw + ASH_B);           // [112][24]: rows 0..20 data, rest 0
    float* Wb  = (float*)(sraw + ASH_B + TEN_B);
    ull*   red = (ull*)sraw;                       // aliases Ash (used only after GEMM reads)

    const int b       = blockIdx.x;
    const int tile    = blockIdx.y;
    const int tid     = threadIdx.x;
    const int cl      = tid & 127;
    const int slice   = tid >> 7;                  // 0 or 1
    const int col     = tile * 128 + cl;
    const int colbase = tile * 128;

    // ---- prime mem-pipeline stage 0 (overlaps staging below) ----
    const int kb0 = slice ? 88 : 0;                // 11 stages of 8 each (KPAD=176)
    float* mbuf = Wb + slice * 4096;               // 2 stages x 2048 floats
    fill_w(mbuf, W1, W2, kb0, colbase, cl);
    cp_commit();

    // ---- staging ----
    for (int i = tid; i < 22 * MEM_DIM; i += 256) {
        int r = i / MEM_DIM;
        int k = i - r * MEM_DIM;
        int node;
        if (r == 0)       node = src_nodes[b];
        else if (r < 11)  node = dst_nei[b * 10 + r - 1];
        else if (r == 11) node = dst_nodes[b];
        else              node = src_nei[b * 10 + r - 12];
        int slot = (r < 11) ? (2 * r) : (2 * (r - 11) + 1);
        Ash[k * ASTRIDE + slot] = memory[(size_t)node * MEM_DIM + k];
    }
    if (tid < (KPAD - MEM_DIM) * ASTRIDE)          // zero pad rows 172..175
        Ash[MEM_DIM * ASTRIDE + tid] = 0.f;

    const float t0 = timestamps[b];
    for (int i = tid; i < TPAD * ASTRIDE; i += 256) {
        int k = i / ASTRIDE;
        int r = i - k * ASTRIDE;
        float v = 0.f;
        if (k < TIME_DIM && r < 21) {
            float delta;
            if (r == 0)      delta = 0.f;
            else if (r < 11) delta = t0 - se[b * 10 + r - 1];
            else             delta = t0 - de[b * 10 + r - 11];
            v = cosf(delta * w_time[k] + phase[k]);
        }
        Ten[i] = v;
    }
    __syncthreads();

    float* resb = g_res + (size_t)b * NROWS * TOK + col;

    // ======== mem projection: pairs (row p, row 11+p) vs {W1, W2} ========
    {
        ull acc[11];
        const ull bi = pack2(b1[col], b2[col]);
#pragma unroll
        for (int p = 0; p < 11; p++) acc[p] = slice == 0 ? bi : 0ull;

        for (int s = 0; s < 11; s++) {
            if (s + 1 < 11) {
                fill_w(mbuf + ((s + 1) & 1) * 2048, W1, W2, kb0 + (s + 1) * 8, colbase, cl);
                cp_commit();
                cp_wait<1>();
            } else {
                cp_wait<0>();
            }
            __syncthreads();

            const float* bufc = mbuf + (s & 1) * 2048;
            const int kb = kb0 + s * 8;
#pragma unroll
            for (int j = 0; j < 8; j++) {
                ull w = pack2(bufc[j * 256 + cl], bufc[j * 256 + 128 + cl]);
                const float* a = Ash + (kb + j) * ASTRIDE;
#pragma unroll
                for (int q = 0; q < 5; q++) {
                    ulonglong2 v = *(const ulonglong2*)(a + 4 * q);
                    acc[2 * q]     = fma2(v.x, w, acc[2 * q]);
                    acc[2 * q + 1] = fma2(v.y, w, acc[2 * q + 1]);
                }
                acc[10] = fma2(*(const ull*)(a + 20), w, acc[10]);
            }
            __syncthreads();   // protect bufc from next stage's fill
        }

        if (slice) {
#pragma unroll
            for (int p = 0; p < 11; p++) red[cl * 11 + p] = acc[p];   // Ash now dead
        }
        __syncthreads();
        if (slice == 0) {
#pragma unroll
            for (int p = 0; p < 11; p++) {
                acc[p] = add2(acc[p], red[cl * 11 + p]);
                float lo, hi; unpack2(acc[p], lo, hi);
                resb[(size_t)p * TOK]        = lo;
                resb[(size_t)(11 + p) * TOK] = hi;
            }
        }
    }

    // ======== time projection: pairs (row 2p, row 2p+1) vs {wt, wt} ========
    {
        const int tb0 = slice ? 56 : 0;            // 7 stages of 8 each (TPAD=112)
        float* tbuf = Wb + slice * 2048;           // 2 stages x 1024 floats
        fill_t(tbuf, Wt, tb0, colbase, cl);        // safe: mem loop fully synced out
        cp_commit();

        ull acc[11];
        const float btc = bt[col];
        const ull bi = pack2(btc, btc);
#pragma unroll
        for (int p = 0; p < 11; p++) acc[p] = slice == 0 ? bi : 0ull;

        for (int s = 0; s < 7; s++) {
            if (s + 1 < 7) {
                fill_t(tbuf + ((s + 1) & 1) * 1024, Wt, tb0 + (s + 1) * 8, colbase, cl);
                cp_commit();
                cp_wait<1>();
            } else {
                cp_wait<0>();
            }
            __syncthreads();

            const float* bufc = tbuf + (s & 1) * 1024;
            const int kb = tb0 + s * 8;
#pragma unroll
            for (int j = 0; j < 8; j++) {
                float wt = bufc[j * 128 + cl];
                ull w = pack2(wt, wt);
                const float* a = Ten + (kb + j) * ASTRIDE;
#pragma unroll
                for (int q = 0; q < 5; q++) {
                    ulonglong2 v = *(const ulonglong2*)(a + 4 * q);
                    acc[2 * q]     = fma2(v.x, w, acc[2 * q]);
                    acc[2 * q + 1] = fma2(v.y, w, acc[2 * q + 1]);
                }
                acc[10] = fma2(*(const ull*)(a + 20), w, acc[10]);
            }
            __syncthreads();
        }

        if (slice) {
#pragma unroll
            for (int p = 0; p < 11; p++) red[cl * 11 + p] = acc[p];
        }
        __syncthreads();
        if (slice == 0) {
#pragma unroll
            for (int p = 0; p < 11; p++) {
                acc[p] = add2(acc[p], red[cl * 11 + p]);
                float lo, hi; unpack2(acc[p], lo, hi);
                resb[(size_t)(22 + 2 * p) * TOK] = lo;
                resb[(size_t)(23 + 2 * p) * TOK] = hi;   // p=10 -> pad row 43
            }
        }
    }
}

// ---------------------------------------------------------------------------
// Kernel B: scatter (R5 proven shape). grid (16,16,8)=2048 CTAs, block 256
// = 64 float4-lanes x 4 token-groups of 16. Streaming stores.
// ---------------------------------------------------------------------------
__global__ void __launch_bounds__(256)
k_scat(float* __restrict__ out)
{
    __shared__ float4 sres[NROWS * 64];     // 45056 B

    const int b     = blockIdx.x;
    const int tile  = blockIdx.y;
    const int slice = blockIdx.z;
    const int tid   = threadIdx.x;
    const int lane  = tid & 63;
    const int grp   = tid >> 6;

    const float4* gresv = (const float4*)g_res;
    const int vrow = TOK / 4;               // 1024

#pragma unroll
    for (int i = tid; i < NROWS * 64; i += 256)
        sres[i] = gresv[(size_t)(b * NROWS + (i >> 6)) * vrow + tile * 64 + (i & 63)];
    __syncthreads();

    float4* outv = (float4*)out;
    const size_t T = (size_t)BATCH * LEN_TOK * vrow;
    const size_t obase = (size_t)(b * LEN_TOK) * vrow + tile * 64 + lane;
    const int t0 = slice * 64 + grp * 16;

#pragma unroll 4
    for (int it = 0; it < 16; it++) {
        const int t = t0 + it;
        int s, d, tm;
        if (t == 0)        { s = 0;  d = 11;    tm = 0;      }
        else if (t < 15)   { s = 0;  d = 0;     tm = 0;      }
        else if (t < 225)  { int j = (t - 15)  / 21; s = 0;  d = 12 + j; tm = 1 + j;  }
        else if (t < 239)  { s = 11; d = 11;    tm = 0;      }
        else if (t < 449)  { int j = (t - 239) / 21; s = 11; d = 1 + j;  tm = 11 + j; }
        else               { s = 0;  d = 11;    tm = 0;      }

        float4 vs = sres[s * 64 + lane];
        float4 vd = sres[d * 64 + lane];
        float4 vt = sres[(22 + tm) * 64 + lane];
        const size_t o = obase + (size_t)t * vrow;
        __stcs(&outv[o],         vs);
        __stcs(&outv[o + T],     vd);
        __stcs(&outv[o + 2 * T], vt);
    }
}

// ---------------------------------------------------------------------------
extern "C" void kernel_launch(void* const* d_in, const int* in_sizes, int n_in,
                              void* d_out, int out_size)
{
    const float* memory      = (const float*)d_in[0];
    const int*   src_nodes   = (const int*)  d_in[1];
    const int*   dst_nodes   = (const int*)  d_in[2];
    const int*   src_nei     = (const int*)  d_in[3];
    const int*   dst_nei     = (const int*)  d_in[4];
    const float* timestamps  = (const float*)d_in[5];
    const float* se          = (const float*)d_in[6];
    const float* de          = (const float*)d_in[7];
    const float* W1          = (const float*)d_in[8];
    const float* b1          = (const float*)d_in[9];
    const float* W2          = (const float*)d_in[10];
    const float* b2          = (const float*)d_in[11];
    const float* Wt          = (const float*)d_in[12];
    const float* bt          = (const float*)d_in[13];
    const float* w_time      = (const float*)d_in[14];
    const float* phase       = (const float*)d_in[15];
    float* out = (float*)d_out;

    cudaFuncSetAttribute(k_proj, cudaFuncAttributeMaxDynamicSharedMemorySize, SMEM_B);

    k_proj<<<dim3(BATCH, TOK / 128), 256, SMEM_B>>>(memory, src_nodes, dst_nodes,
                                                    src_nei, dst_nei,
                                                    timestamps, se, de,
                                                    W1, b1, W2, b2, Wt, bt,
                                                    w_time, phase);
    k_scat<<<dim3(BATCH, TOK / 256, 8), 256>>>(out);
}

// round 9
// speedup vs baseline: 2.2236x; 1.0753x over previous
#include <cuda_runtime.h>
#include <math.h>
#include <stdint.h>

#define BATCH     16
#define MEM_DIM   172
#define KPAD      176       // MEM_DIM padded (11 stages x 8 x 2 slices)
#define TOK       4096
#define TIME_DIM  100
#define TPAD      112       // TIME_DIM padded (7 stages x 8 x 2 slices)
#define LEN_TOK   512
#define NROWS     44        // 22 cat + 21 texp + 1 pad
#define ASTRIDE   24        // padded smem row stride (16B aligned)

typedef unsigned long long ull;

// Projected rows scratch: [batch][44][4096] f32 = 11.5 MB (L2-resident).
__device__ __align__(16) float g_res[BATCH * NROWS * TOK];

__device__ __forceinline__ ull pack2(float lo, float hi) {
    ull d; asm("mov.b64 %0, {%1, %2};" : "=l"(d) : "f"(lo), "f"(hi)); return d;
}
__device__ __forceinline__ void unpack2(ull v, float& lo, float& hi) {
    asm("mov.b64 {%0, %1}, %2;" : "=f"(lo), "=f"(hi) : "l"(v));
}
__device__ __forceinline__ ull fma2(ull a, ull b, ull c) {
    ull d; asm("fma.rn.f32x2 %0, %1, %2, %3;" : "=l"(d) : "l"(a), "l"(b), "l"(c)); return d;
}
__device__ __forceinline__ ull add2(ull a, ull b) {
    ull d; asm("add.rn.f32x2 %0, %1, %2;" : "=l"(d) : "l"(a), "l"(b)); return d;
}
__device__ __forceinline__ uint32_t s2u(const void* p) {
    return (uint32_t)__cvta_generic_to_shared(p);
}
__device__ __forceinline__ void cp16(uint32_t dst, const void* src) {
    asm volatile("cp.async.cg.shared.global [%0], [%1], 16;" :: "r"(dst), "l"(src));
}
__device__ __forceinline__ void cp_commit() { asm volatile("cp.async.commit_group;"); }
template<int N> __device__ __forceinline__ void cp_wait() {
    asm volatile("cp.async.wait_group %0;" :: "n"(N) : "memory");
}

// Stage fill: 8 k-rows x 128 cols of W1/W2 -> buf[k][0..127]=W1, [k][128..255]=W2.
__device__ __forceinline__ void fill_w(float* buf, const float* W1, const float* W2,
                                       int kbase, int colbase, int cl)
{
#pragma unroll
    for (int j = 0; j < 4; j++) {
        int c   = cl + 128 * j;           // 0..511
        int mat = c >> 8;
        int k   = (c >> 5) & 7;
        int c16 = c & 31;
        int krow = kbase + k; if (krow > MEM_DIM - 1) krow = MEM_DIM - 1;  // pad rows: A=0
        const float* src = (mat ? W2 : W1) + (size_t)krow * TOK + colbase + c16 * 4;
        cp16(s2u(buf + k * 256 + mat * 128 + c16 * 4), src);
    }
}

// Stage fill for Wt: 8 k-rows x 128 cols.
__device__ __forceinline__ void fill_t(float* buf, const float* Wt,
                                       int kbase, int colbase, int cl)
{
#pragma unroll
    for (int j = 0; j < 2; j++) {
        int c   = cl + 128 * j;           // 0..255
        int k   = c >> 5;
        int c16 = c & 31;
        int krow = kbase + k; if (krow > TIME_DIM - 1) krow = TIME_DIM - 1;
        cp16(s2u(buf + k * 128 + c16 * 4), Wt + (size_t)krow * TOK + colbase + c16 * 4);
    }
}

// Smem: Ash [176][24] = 16896 B, then Wb = 32768 B.
// After the mem GEMM, Wb is reused: Ten [112][24] = 10752 B at Wb, tbuf (16 KB) after.
// red (cross-slice partials) aliases Ash once the GEMM reads are barrier-complete.
#define ASH_B  (KPAD * ASTRIDE * 4)
#define WB_B   (2 * 2 * 8 * 256 * 4)
#define SMEM_B (ASH_B + WB_B)            // 49664 B -> 4 CTAs/SM -> single wave

// ---------------------------------------------------------------------------
// Kernel A: projections. grid (16 b, 32 tiles of 128 cols), block 256
// (= 128 cols x 2 k-slices). cp.async double-buffered W stream, single wave.
// g_res rows: 0..21 = cat_mem, 22..42 = texp, 43 = pad.
// ---------------------------------------------------------------------------
__global__ void __launch_bounds__(256, 4)
k_proj(const float* __restrict__ memory,
       const int*   __restrict__ src_nodes,
       const int*   __restrict__ dst_nodes,
       const int*   __restrict__ src_nei,
       const int*   __restrict__ dst_nei,
       const float* __restrict__ timestamps,
       const float* __restrict__ se,
       const float* __restrict__ de,
       const float* __restrict__ W1, const float* __restrict__ b1,
       const float* __restrict__ W2, const float* __restrict__ b2,
       const float* __restrict__ Wt, const float* __restrict__ bt,
       const float* __restrict__ w_time,
       const float* __restrict__ phase)
{
    extern __shared__ __align__(16) char sraw[];
    float* Ash = (float*)sraw;                     // [176][24]: slot 2i=row i, 2i+1=row 11+i
    float* Wb  = (float*)(sraw + ASH_B);           // mem-loop W stages
    float* Ten = Wb;                               // [112][24], valid after mem loop
    float* Tw  = Wb + TPAD * ASTRIDE;              // time-loop W stages (16 KB)
    ull*   red = (ull*)sraw;                       // aliases Ash (barrier-protected)

    const int b       = blockIdx.x;
    const int tile    = blockIdx.y;
    const int tid     = threadIdx.x;
    const int cl      = tid & 127;
    const int slice   = tid >> 7;                  // 0 or 1
    const int col     = tile * 128 + cl;
    const int colbase = tile * 128;

    // prime mem-pipeline stage 0 (overlaps A staging)
    const int kb0 = slice ? 88 : 0;                // 11 stages of 8 each
    float* mbuf = Wb + slice * 4096;               // 2 stages x 2048 floats
    fill_w(mbuf, W1, W2, kb0, colbase, cl);
    cp_commit();

    // ---- stage A ----
    for (int i = tid; i < 22 * MEM_DIM; i += 256) {
        int r = i / MEM_DIM;
        int k = i - r * MEM_DIM;
        int node;
        if (r == 0)       node = src_nodes[b];
        else if (r < 11)  node = dst_nei[b * 10 + r - 1];
        else if (r == 11) node = dst_nodes[b];
        else              node = src_nei[b * 10 + r - 12];
        int slot = (r < 11) ? (2 * r) : (2 * (r - 11) + 1);
        Ash[k * ASTRIDE + slot] = memory[(size_t)node * MEM_DIM + k];
    }
    if (tid < (KPAD - MEM_DIM) * ASTRIDE)          // zero pad rows 172..175
        Ash[MEM_DIM * ASTRIDE + tid] = 0.f;
    __syncthreads();

    float* resb = g_res + (size_t)b * NROWS * TOK + col;

    // ======== mem projection: pairs (row p, row 11+p) vs {W1, W2} ========
    {
        ull acc[11];
        const ull bi = pack2(b1[col], b2[col]);
#pragma unroll
        for (int p = 0; p < 11; p++) acc[p] = slice == 0 ? bi : 0ull;

        for (int s = 0; s < 11; s++) {
            if (s + 1 < 11) {
                fill_w(mbuf + ((s + 1) & 1) * 2048, W1, W2, kb0 + (s + 1) * 8, colbase, cl);
                cp_commit();
                cp_wait<1>();
            } else {
                cp_wait<0>();
            }
            __syncthreads();

            const float* bufc = mbuf + (s & 1) * 2048;
            const int kb = kb0 + s * 8;
#pragma unroll
            for (int j = 0; j < 8; j++) {
                ull w = pack2(bufc[j * 256 + cl], bufc[j * 256 + 128 + cl]);
                const float* a = Ash + (kb + j) * ASTRIDE;
#pragma unroll
                for (int q = 0; q < 5; q++) {
                    ulonglong2 v = *(const ulonglong2*)(a + 4 * q);
                    acc[2 * q]     = fma2(v.x, w, acc[2 * q]);
                    acc[2 * q + 1] = fma2(v.y, w, acc[2 * q + 1]);
                }
                acc[10] = fma2(*(const ull*)(a + 20), w, acc[10]);
            }
            __syncthreads();   // all threads done with this stage buffer + Ash stage
        }

        // prime time-pipeline stage 0 now (Tw safe: all mem compute complete)
        const int tb0 = slice ? 56 : 0;
        fill_t(Tw + slice * 2048, Wt, tb0, colbase, cl);
        cp_commit();

        if (slice) {
#pragma unroll
            for (int p = 0; p < 11; p++) red[cl * 11 + p] = acc[p];   // Ash dead
        }
        __syncthreads();
        if (slice == 0) {
#pragma unroll
            for (int p = 0; p < 11; p++) {
                acc[p] = add2(acc[p], red[cl * 11 + p]);
                float lo, hi; unpack2(acc[p], lo, hi);
                resb[(size_t)p * TOK]        = lo;
                resb[(size_t)(11 + p) * TOK] = hi;
            }
        }
    }
    __syncthreads();

    // ---- stage Ten (into the dead mem-W buffer region) ----
    const float t0v = timestamps[b];
    for (int i = tid; i < TPAD * ASTRIDE; i += 256) {
        int k = i / ASTRIDE;
        int r = i - k * ASTRIDE;
        float v = 0.f;
        if (k < TIME_DIM && r < 21) {
            float delta;
            if (r == 0)      delta = 0.f;
            else if (r < 11) delta = t0v - se[b * 10 + r - 1];
            else             delta = t0v - de[b * 10 + r - 11];
            v = cosf(delta * w_time[k] + phase[k]);
        }
        Ten[i] = v;
    }
    __syncthreads();

    // ======== time projection: pairs (row 2p, row 2p+1) vs {wt, wt} ========
    {
        const int tb0 = slice ? 56 : 0;            // 7 stages of 8 each
        float* tbuf = Tw + slice * 2048;           // 2 stages x 1024 floats

        ull acc[11];
        const float btc = bt[col];
        const ull bi = pack2(btc, btc);
#pragma unroll
        for (int p = 0; p < 11; p++) acc[p] = slice == 0 ? bi : 0ull;

        for (int s = 0; s < 7; s++) {
            if (s + 1 < 7) {
                fill_t(tbuf + ((s + 1) & 1) * 1024, Wt, tb0 + (s + 1) * 8, colbase, cl);
                cp_commit();
                cp_wait<1>();
            } else {
                cp_wait<0>();
            }
            __syncthreads();

            const float* bufc = tbuf + (s & 1) * 1024;
            const int kb = tb0 + s * 8;
#pragma unroll
            for (int j = 0; j < 8; j++) {
                float wt = bufc[j * 128 + cl];
                ull w = pack2(wt, wt);
                const float* a = Ten + (kb + j) * ASTRIDE;
#pragma unroll
                for (int q = 0; q < 5; q++) {
                    ulonglong2 v = *(const ulonglong2*)(a + 4 * q);
                    acc[2 * q]     = fma2(v.x, w, acc[2 * q]);
                    acc[2 * q + 1] = fma2(v.y, w, acc[2 * q + 1]);
                }
                acc[10] = fma2(*(const ull*)(a + 20), w, acc[10]);
            }
            __syncthreads();
        }

        if (slice) {
#pragma unroll
            for (int p = 0; p < 11; p++) red[cl * 11 + p] = acc[p];
        }
        __syncthreads();
        if (slice == 0) {
#pragma unroll
            for (int p = 0; p < 11; p++) {
                acc[p] = add2(acc[p], red[cl * 11 + p]);
                float lo, hi; unpack2(acc[p], lo, hi);
                resb[(size_t)(22 + 2 * p) * TOK] = lo;
                resb[(size_t)(23 + 2 * p) * TOK] = hi;   // p=10 -> pad row 43
            }
        }
    }
}

// ---------------------------------------------------------------------------
// Kernel B: run-grouped scatter. Tokens come in 21-token runs sharing one
// (s,d,tm) triple -> grid (16 b, 16 tiles of 256 cols, 25 runs), block 256
// = 64 float4-lanes x 4 token subgroups. Each thread: 3 LDG.128 into regs,
// then a pure __stcs STG.128 stream. No smem, no barriers.
// ---------------------------------------------------------------------------
__global__ void __launch_bounds__(256)
k_scat(float* __restrict__ out)
{
    const int b    = blockIdx.x;
    const int tile = blockIdx.y;
    const int z    = blockIdx.z;
    const int tid  = threadIdx.x;
    const int lane = tid & 63;
    const int sub  = tid >> 6;

    int t0, n, rS, rD, rT;
    if (z < 10)       { t0 = 15 + 21 * z;  n = 21; rS = 0;  rD = 12 + z; rT = 23 + z; }
    else if (z < 20)  { int q = z - 10; t0 = 239 + 21 * q; n = 21; rS = 11; rD = 1 + q; rT = 33 + q; }
    else if (z == 20) { t0 = 0;   n = 15; rS = 0;  rD = 11; rT = 22; }   // t=0 special
    else if (z == 21) { t0 = 225; n = 14; rS = 11; rD = 11; rT = 22; }
    else              { t0 = 449 + 21 * (z - 22); n = 21; rS = 0; rD = 11; rT = 22; }

    const float4* gresv = (const float4*)g_res;
    const int vrow = TOK / 4;                    // 1024
    const size_t rbase = (size_t)b * NROWS * vrow + tile * 64 + lane;
    const float4 vs = __ldg(&gresv[rbase + (size_t)rS * vrow]);
    const float4 vd = __ldg(&gresv[rbase + (size_t)rD * vrow]);
    const float4 vt = __ldg(&gresv[rbase + (size_t)rT * vrow]);

    float4* outv = (float4*)out;
    const size_t T = (size_t)BATCH * LEN_TOK * vrow;
    const size_t obase = (size_t)(b * LEN_TOK) * vrow + tile * 64 + lane;

    if (z == 20) {
        // t=0: dst=row11; t=1..14: dst=row0 (== vs)
        for (int i = sub; i < n; i += 4) {
            const int t = t0 + i;
            const size_t o = obase + (size_t)t * vrow;
            __stcs(&outv[o],         vs);
            __stcs(&outv[o + T],     (t == 0) ? vd : vs);
            __stcs(&outv[o + 2 * T], vt);
        }
    } else {
        for (int i = sub; i < n; i += 4) {
            const size_t o = obase + (size_t)(t0 + i) * vrow;
            __stcs(&outv[o],         vs);
            __stcs(&outv[o + T],     vd);
            __stcs(&outv[o + 2 * T], vt);
        }
    }
}

// ---------------------------------------------------------------------------
extern "C" void kernel_launch(void* const* d_in, const int* in_sizes, int n_in,
                              void* d_out, int out_size)
{
    const float* memory      = (const float*)d_in[0];
    const int*   src_nodes   = (const int*)  d_in[1];
    const int*   dst_nodes   = (const int*)  d_in[2];
    const int*   src_nei     = (const int*)  d_in[3];
    const int*   dst_nei     = (const int*)  d_in[4];
    const float* timestamps  = (const float*)d_in[5];
    const float* se          = (const float*)d_in[6];
    const float* de          = (const float*)d_in[7];
    const float* W1          = (const float*)d_in[8];
    const float* b1          = (const float*)d_in[9];
    const float* W2          = (const float*)d_in[10];
    const float* b2          = (const float*)d_in[11];
    const float* Wt          = (const float*)d_in[12];
    const float* bt          = (const float*)d_in[13];
    const float* w_time      = (const float*)d_in[14];
    const float* phase       = (const float*)d_in[15];
    float* out = (float*)d_out;

    cudaFuncSetAttribute(k_proj, cudaFuncAttributeMaxDynamicSharedMemorySize, SMEM_B);

    k_proj<<<dim3(BATCH, TOK / 128), 256, SMEM_B>>>(memory, src_nodes, dst_nodes,
                                                    src_nei, dst_nei,
                                                    timestamps, se, de,
                                                    W1, b1, W2, b2, Wt, bt,
                                                    w_time, phase);
    k_scat<<<dim3(BATCH, TOK / 256, 25), 256>>>(out);
}